// round 17
// baseline (speedup 1.0000x reference)
#include <cuda_runtime.h>
#include <cuda_bf16.h>
#include <math.h>
#include <stdint.h>

#define BATCH 4096
#define NDIM  64
#define HID   512
#define GB    8

__device__ float g_G0[HID * NDIM];
__device__ float g_maskB[3 * BATCH * HID];
__device__ __align__(16) __nv_bfloat16 g_WT[2][HID * HID];
__device__ __align__(16) __nv_bfloat16 g_G0T[NDIM * HID];
__device__ __align__(16) __nv_bfloat16 g_U[(size_t)(BATCH / 2) * 128 * HID];
__device__ __align__(16) float2 g_WP[3 * HID * 256];
__device__ __align__(16) float2 g_WinP[NDIM * 256];
__device__ __align__(16) float2 g_G0P[NDIM * 256];
__device__ __align__(16) float  g_WoutT[HID * NDIM];
__device__ unsigned g_flag[BATCH / GB];

#define ZP_A     0
#define ZP_B     133120
#define Z_SMEM   169984
#define A_STRIDE 1040
#define B_STRIDE 144

__device__ __forceinline__ uint32_t smem_u32(const void* p) {
    uint32_t a;
    asm("{ .reg .u64 t; cvta.to.shared.u64 t, %1; cvt.u32.u64 %0, t; }" : "=r"(a) : "l"(p));
    return a;
}
#define CP16(dst, src)  asm volatile("cp.async.cg.shared.global [%0], [%1], 16;" :: "r"(dst), "l"(src))
#define CP_COMMIT()     asm volatile("cp.async.commit_group;" ::: "memory")
#define CP_WAIT(n)      asm volatile("cp.async.wait_group %0;" :: "n"(n) : "memory")
#define PDL_TRIGGER()   asm volatile("griddepcontrol.launch_dependents;" ::: "memory")

__device__ __forceinline__ void ldsm4(uint32_t addr, uint32_t& r0, uint32_t& r1,
                                      uint32_t& r2, uint32_t& r3) {
    asm volatile("ldmatrix.sync.aligned.m8n8.x4.shared.b16 {%0,%1,%2,%3}, [%4];"
        : "=r"(r0), "=r"(r1), "=r"(r2), "=r"(r3) : "r"(addr));
}
__device__ __forceinline__ void mma_bf16(float* c, const uint32_t* a, const uint32_t* b) {
    asm volatile("mma.sync.aligned.m16n8k16.row.col.f32.bf16.bf16.f32 "
        "{%0,%1,%2,%3}, {%4,%5,%6,%7}, {%8,%9}, {%0,%1,%2,%3};"
        : "+f"(c[0]), "+f"(c[1]), "+f"(c[2]), "+f"(c[3])
        : "r"(a[0]), "r"(a[1]), "r"(a[2]), "r"(a[3]), "r"(b[0]), "r"(b[1]));
}
__device__ __forceinline__ uint32_t pack_bf16(float lo, float hi) {
    uint32_t pk;
    asm("cvt.rn.bf16x2.f32 %0, %1, %2;" : "=r"(pk) : "f"(hi), "f"(lo));
    return pk;
}

// ---------------- prep ----------------
__global__ void prep_reset() { g_flag[blockIdx.x * 64 + threadIdx.x] = 0u; }
__global__ void prep_g0(const float* __restrict__ Wh, const float* __restrict__ Win) {
    int i = blockIdx.x, d = threadIdx.x;
    float acc = 0.f;
    for (int j = 0; j < HID; j++) acc += Wh[i * HID + j] * Win[j * NDIM + d];
    g_G0[i * NDIM + d] = acc;
}
__global__ void prep_wt(const float* __restrict__ Wh) {
    int li = blockIdx.x >> 9, n = blockIdx.x & 511;
    const float* base = Wh + (size_t)(li + 1) * HID * HID;
    __nv_bfloat16* dst = g_WT[li] + (size_t)n * HID;
    for (int k = threadIdx.x; k < HID; k += 128)
        dst[k] = __float2bfloat16(base[(size_t)k * HID + n]);
}
__global__ void prep_g0t() {
    int d = blockIdx.x, h = threadIdx.x;
    g_G0T[d * HID + h] = __float2bfloat16(g_G0[h * NDIM + d]);
}
__global__ void prep_wp(const float* __restrict__ Wh) {
    int l = blockIdx.x >> 8, tt = blockIdx.x & 255;
    int k = threadIdx.x;
    const float* base = Wh + (size_t)l * HID * HID;
    g_WP[((size_t)l * HID + k) * 256 + tt] =
        make_float2(base[(size_t)tt * HID + k], base[(size_t)(tt + 256) * HID + k]);
}
__global__ void prep_winp(const float* __restrict__ Win) {
    int tt = blockIdx.x, d = threadIdx.x;
    g_WinP[d * 256 + tt] = make_float2(Win[tt * NDIM + d], Win[(tt + 256) * NDIM + d]);
    g_G0P [d * 256 + tt] = make_float2(g_G0[tt * NDIM + d], g_G0[(tt + 256) * NDIM + d]);
}
__global__ void prep_woutt(const float* __restrict__ Wout) {
    g_WoutT[blockIdx.x * NDIM + threadIdx.x] = Wout[threadIdx.x * HID + blockIdx.x];
}

// ---------------- fwd (unchanged math; + PDL trigger + done-flag) ----------
union F8 { float4 v[2]; float f[GB]; };

__global__ __launch_bounds__(256) void fwd_kernel(
    const float* __restrict__ x,
    const float* __restrict__ bin, const float* __restrict__ bh,
    const float* __restrict__ bout, float* __restrict__ out)
{
    extern __shared__ float sm[];
    float* sxA = sm;
    float* sxZ = sxA + NDIM * GB;
    float* sxD = sxZ + NDIM * GB;
    float* shA = sxD + NDIM * GB;
    float* shB = shA + HID * GB;
    float* sv  = shB + HID * GB;

    PDL_TRIGGER();

    int t  = threadIdx.x, t1 = t + 256;
    int b0 = blockIdx.x * GB;

    for (int i = t; i < GB * 192; i += 256) {
        int g = i / 192, c = i % 192;
        float v = x[(b0 + g) * 192 + c];
        if (c < 64)       sxA[c * GB + g] = v;
        else if (c < 128) sxD[(c - 64) * GB + g] = v;
        else              sxZ[(c - 128) * GB + g] = v;
    }
    __syncthreads();

    {
        float aA[2][GB], aB[2][GB], aV[2][GB];
        float bi0 = bin[t], bi1 = bin[t1];
#pragma unroll
        for (int g = 0; g < GB; g++) {
            aA[0][g] = bi0; aB[0][g] = bi0; aV[0][g] = 0.f;
            aA[1][g] = bi1; aB[1][g] = bi1; aV[1][g] = 0.f;
        }
#pragma unroll 4
        for (int d = 0; d < NDIM; d++) {
            float2 wp = g_WinP[d * 256 + t];
            float2 gp = g_G0P [d * 256 + t];
            F8 xa, xz, xd;
            xa.v[0] = *(const float4*)&sxA[d * GB]; xa.v[1] = *(const float4*)&sxA[d * GB + 4];
            xz.v[0] = *(const float4*)&sxZ[d * GB]; xz.v[1] = *(const float4*)&sxZ[d * GB + 4];
            xd.v[0] = *(const float4*)&sxD[d * GB]; xd.v[1] = *(const float4*)&sxD[d * GB + 4];
#pragma unroll
            for (int g = 0; g < GB; g++) {
                aA[0][g] += wp.x * xa.f[g];  aA[1][g] += wp.y * xa.f[g];
                aB[0][g] += wp.x * xz.f[g];  aB[1][g] += wp.y * xz.f[g];
                aV[0][g] += gp.x * xd.f[g];  aV[1][g] += gp.y * xd.f[g];
            }
        }
#pragma unroll
        for (int g = 0; g < GB; g++) {
            shA[t  * GB + g] = aA[0][g]; shA[t1 * GB + g] = aA[1][g];
            shB[t  * GB + g] = aB[0][g]; shB[t1 * GB + g] = aB[1][g];
            sv [t  * GB + g] = aV[0][g]; sv [t1 * GB + g] = aV[1][g];
        }
    }
    __syncthreads();

#pragma unroll 1
    for (int l = 0; l < 3; l++) {
        const float2* wpL = g_WP + (size_t)l * HID * 256;
        float bias0 = bh[l * HID + t], bias1 = bh[l * HID + t1];

        float aA[2][GB], aB[2][GB], aV[2][GB];
#pragma unroll
        for (int g = 0; g < GB; g++) {
            aA[0][g] = bias0; aB[0][g] = bias0; aV[0][g] = 0.f;
            aA[1][g] = bias1; aB[1][g] = bias1; aV[1][g] = 0.f;
        }
#pragma unroll 4
        for (int k = 0; k < HID; k++) {
            float2 wp = wpL[k * 256 + t];
            F8 ha, hb, vv;
            ha.v[0] = *(const float4*)&shA[k * GB]; ha.v[1] = *(const float4*)&shA[k * GB + 4];
            hb.v[0] = *(const float4*)&shB[k * GB]; hb.v[1] = *(const float4*)&shB[k * GB + 4];
            if (l > 0) {
                vv.v[0] = *(const float4*)&sv[k * GB]; vv.v[1] = *(const float4*)&sv[k * GB + 4];
            }
#pragma unroll
            for (int g = 0; g < GB; g++) {
                aA[0][g] += wp.x * ha.f[g];  aA[1][g] += wp.y * ha.f[g];
                aB[0][g] += wp.x * hb.f[g];  aB[1][g] += wp.y * hb.f[g];
                if (l > 0) { aV[0][g] += wp.x * vv.f[g]; aV[1][g] += wp.y * vv.f[g]; }
            }
        }
        __syncthreads();
#pragma unroll
        for (int g = 0; g < GB; g++) {
            shA[t  * GB + g] = fmaxf(aA[0][g], 0.f);
            shA[t1 * GB + g] = fmaxf(aA[1][g], 0.f);
            shB[t  * GB + g] = fmaxf(aB[0][g], 0.f);
            shB[t1 * GB + g] = fmaxf(aB[1][g], 0.f);
            if (l > 0) { sv[t * GB + g] = aV[0][g]; sv[t1 * GB + g] = aV[1][g]; }
        }
        __syncthreads();

#pragma unroll
        for (int g = 0; g < GB; g++) {
            aA[0][g] = bias0; aB[0][g] = bias0;
            aA[1][g] = bias1; aB[1][g] = bias1;
        }
#pragma unroll 4
        for (int k = 0; k < HID; k++) {
            float2 wp = wpL[k * 256 + t];
            F8 ha, hb;
            ha.v[0] = *(const float4*)&shA[k * GB]; ha.v[1] = *(const float4*)&shA[k * GB + 4];
            hb.v[0] = *(const float4*)&shB[k * GB]; hb.v[1] = *(const float4*)&shB[k * GB + 4];
#pragma unroll
            for (int g = 0; g < GB; g++) {
                aA[0][g] += wp.x * ha.f[g];  aA[1][g] += wp.y * ha.f[g];
                aB[0][g] += wp.x * hb.f[g];  aB[1][g] += wp.y * hb.f[g];
            }
        }
#pragma unroll
        for (int g = 0; g < GB; g++) {
            float dA0 = aA[0][g] > 0.f ? 1.f : 0.f;
            float dA1 = aA[1][g] > 0.f ? 1.f : 0.f;
            sv[t  * GB + g] *= dA0;
            sv[t1 * GB + g] *= dA1;
            g_maskB[((size_t)l * BATCH + (b0 + g)) * HID + t]  = aB[0][g] > 0.f ? 1.f : 0.f;
            g_maskB[((size_t)l * BATCH + (b0 + g)) * HID + t1] = aB[1][g] > 0.f ? 1.f : 0.f;
        }
        __syncthreads();
    }

    {
        float aO[2][GB], aV[2][GB];
#pragma unroll
        for (int g = 0; g < GB; g++) {
            aO[0][g] = 0.f; aV[0][g] = 0.f;
            aO[1][g] = 0.f; aV[1][g] = 0.f;
        }
        int s = t >> 5, n0 = t & 31, n1 = n0 + 32;
#pragma unroll 4
        for (int hh = 0; hh < 64; hh++) {
            int h = s * 64 + hh;
            float w0 = g_WoutT[h * NDIM + n0];
            float w1 = g_WoutT[h * NDIM + n1];
            F8 ha, vv;
            ha.v[0] = *(const float4*)&shA[h * GB]; ha.v[1] = *(const float4*)&shA[h * GB + 4];
            vv.v[0] = *(const float4*)&sv [h * GB]; vv.v[1] = *(const float4*)&sv [h * GB + 4];
#pragma unroll
            for (int g = 0; g < GB; g++) {
                aO[0][g] += w0 * ha.f[g];  aO[1][g] += w1 * ha.f[g];
                aV[0][g] += w0 * vv.f[g];  aV[1][g] += w1 * vv.f[g];
            }
        }
        float* red = shB;
#pragma unroll
        for (int g = 0; g < GB; g++) {
            red[(g * 64 + n0) * 8 + s] = aO[0][g];
            red[(g * 64 + n1) * 8 + s] = aO[1][g];
        }
        __syncthreads();
        if (s == 0) {
#pragma unroll
            for (int g = 0; g < GB; g++) {
                float s0 = bout[n0], s1 = bout[n1];
                for (int ss = 0; ss < 8; ss++) {
                    s0 += red[(g * 64 + n0) * 8 + ss];
                    s1 += red[(g * 64 + n1) * 8 + ss];
                }
                out[(size_t)(b0 + g) * 192 + n0] = s0;
                out[(size_t)(b0 + g) * 192 + n1] = s1;
            }
        }
        __syncthreads();
#pragma unroll
        for (int g = 0; g < GB; g++) {
            red[(g * 64 + n0) * 8 + s] = aV[0][g];
            red[(g * 64 + n1) * 8 + s] = aV[1][g];
        }
        __syncthreads();
        if (s == 0) {
#pragma unroll
            for (int g = 0; g < GB; g++) {
                float s0 = 0.f, s1 = 0.f;
                for (int ss = 0; ss < 8; ss++) {
                    s0 += red[(g * 64 + n0) * 8 + ss];
                    s1 += red[(g * 64 + n1) * 8 + ss];
                }
                out[(size_t)(b0 + g) * 192 + 64 + n0] = s0;
                out[(size_t)(b0 + g) * 192 + 64 + n1] = s1;
            }
        }
    }

    __threadfence();
    __syncthreads();
    if (t == 0) atomicExch(&g_flag[blockIdx.x], 1u);
}

// ---------------- z (masks from global; flag-gated) ----------
__device__ __forceinline__ void issue_b128(const __nv_bfloat16* __restrict__ Bg,
                                           int ns, int kc, uint32_t sB, int t) {
#pragma unroll
    for (int i = 0; i < 4; i++) {
        int flat = t + 256 * i;
        int row = flat >> 3, seg = flat & 7;
        CP16(sB + row * B_STRIDE + seg * 16,
             (const char*)(Bg + (size_t)(ns * 128 + row) * HID + kc * 64 + seg * 8));
    }
    CP_COMMIT();
}

__device__ void gemm512(const __nv_bfloat16* __restrict__ Bg,
                        const float* __restrict__ mb,   // global mask base, item stride HID
                        __nv_bfloat16* __restrict__ Ug,
                        uint32_t smu, int t)
{
    const int w = t >> 5, l = t & 31;
    const int wm = w & 3, wn = w >> 2;
    const uint32_t sA = smu + ZP_A;
    const uint32_t aRowB = (wm * 32 + (l & 15)) * A_STRIDE + ((l >> 4) << 4);
    const uint32_t bRowB = ((l & 7) + ((l >> 4) << 3)) * B_STRIDE + (((l >> 3) & 1) << 4);

#pragma unroll 1
    for (int ns = 0; ns < 4; ns++) {
        float c[2][8][4];
#pragma unroll
        for (int mt = 0; mt < 2; mt++)
#pragma unroll
            for (int nt = 0; nt < 8; nt++)
#pragma unroll
                for (int q = 0; q < 4; q++) c[mt][nt][q] = 0.f;

        issue_b128(Bg, ns, 0, smu + ZP_B, t);
        issue_b128(Bg, ns, 1, smu + ZP_B + 18432, t);

#pragma unroll
        for (int kc = 0; kc < 8; kc++) {
            if (kc == 7) { CP_WAIT(0); } else { CP_WAIT(1); }
            __syncthreads();
            uint32_t sB = smu + ZP_B + (kc & 1) * 18432;
#pragma unroll
            for (int ks = 0; ks < 4; ks++) {
                uint32_t a[2][4];
#pragma unroll
                for (int mt = 0; mt < 2; mt++)
                    ldsm4(sA + aRowB + mt * 16 * A_STRIDE + (kc * 64 + ks * 16) * 2,
                          a[mt][0], a[mt][1], a[mt][2], a[mt][3]);
                uint32_t b[8][2];
#pragma unroll
                for (int p = 0; p < 4; p++) {
                    uint32_t addr = sB + (wn * 64 + p * 16) * B_STRIDE + bRowB + ks * 32;
                    uint32_t r0, r1, r2, r3;
                    ldsm4(addr, r0, r1, r2, r3);
                    b[2 * p][0] = r0; b[2 * p][1] = r1;
                    b[2 * p + 1][0] = r2; b[2 * p + 1][1] = r3;
                }
#pragma unroll
                for (int mt = 0; mt < 2; mt++)
#pragma unroll
                    for (int nt = 0; nt < 8; nt++)
                        mma_bf16(c[mt][nt], a[mt], b[nt]);
            }
            __syncthreads();
            if (kc + 2 < 8) issue_b128(Bg, ns, kc + 2, smu + ZP_B + (kc & 1) * 18432, t);
        }

#pragma unroll
        for (int mt = 0; mt < 2; mt++) {
            int r0 = wm * 32 + mt * 16 + (l >> 2);
            const float* mk = mb + ((wm * 32 + mt * 16) >> 6) * HID;
#pragma unroll
            for (int nt = 0; nt < 8; nt++) {
                int col = ns * 128 + wn * 64 + nt * 8 + (l & 3) * 2;
                float m0 = mk[col], m1 = mk[col + 1];
                *(uint32_t*)&Ug[(size_t)r0 * HID + col] =
                    pack_bf16(c[mt][nt][0] * m0, c[mt][nt][1] * m1);
                *(uint32_t*)&Ug[(size_t)(r0 + 8) * HID + col] =
                    pack_bf16(c[mt][nt][2] * m0, c[mt][nt][3] * m1);
            }
        }
    }
    __syncthreads();

#pragma unroll
    for (int i = 0; i < 32; i++) {
        int flat = t + 256 * i;
        int row = flat >> 6, seg = flat & 63;
        CP16(sA + row * A_STRIDE + seg * 16, (const char*)(Ug + (size_t)row * HID + seg * 8));
    }
    CP_COMMIT();
    CP_WAIT(0);
    __syncthreads();
}

__device__ void gemm_final(const __nv_bfloat16* __restrict__ Bg,
                           float* __restrict__ out, int b0, uint32_t smu, int t)
{
    const int w = t >> 5, l = t & 31;
    const uint32_t sA = smu + ZP_A;
    const uint32_t aRowB = (w * 16 + (l & 15)) * A_STRIDE + ((l >> 4) << 4);
    const uint32_t bRowB = ((l & 7) + ((l >> 4) << 3)) * B_STRIDE + (((l >> 3) & 1) << 4);

    float c[8][4];
#pragma unroll
    for (int nt = 0; nt < 8; nt++)
#pragma unroll
        for (int q = 0; q < 4; q++) c[nt][q] = 0.f;

    auto issue64 = [&](int kc, uint32_t sB) {
#pragma unroll
        for (int i = 0; i < 2; i++) {
            int flat = t + 256 * i;
            int row = flat >> 3, seg = flat & 7;
            CP16(sB + row * B_STRIDE + seg * 16,
                 (const char*)(Bg + (size_t)row * HID + kc * 64 + seg * 8));
        }
        CP_COMMIT();
    };

    issue64(0, smu + ZP_B);
    issue64(1, smu + ZP_B + 18432);

#pragma unroll
    for (int kc = 0; kc < 8; kc++) {
        if (kc == 7) { CP_WAIT(0); } else { CP_WAIT(1); }
        __syncthreads();
        uint32_t sB = smu + ZP_B + (kc & 1) * 18432;
#pragma unroll
        for (int ks = 0; ks < 4; ks++) {
            uint32_t a[4];
            ldsm4(sA + aRowB + (kc * 64 + ks * 16) * 2, a[0], a[1], a[2], a[3]);
            uint32_t b[8][2];
#pragma unroll
            for (int p = 0; p < 4; p++) {
                uint32_t addr = sB + (p * 16) * B_STRIDE + bRowB + ks * 32;
                uint32_t r0, r1, r2, r3;
                ldsm4(addr, r0, r1, r2, r3);
                b[2 * p][0] = r0; b[2 * p][1] = r1;
                b[2 * p + 1][0] = r2; b[2 * p + 1][1] = r3;
            }
#pragma unroll
            for (int nt = 0; nt < 8; nt++)
                mma_bf16(c[nt], a, b[nt]);
        }
        __syncthreads();
        if (kc + 2 < 8) issue64(kc + 2, smu + ZP_B + (kc & 1) * 18432);
    }

    float s0 = 0.f, s1 = 0.f;
#pragma unroll
    for (int nt = 0; nt < 8; nt++) {
        s0 += c[nt][0] * c[nt][0] + c[nt][1] * c[nt][1];
        s1 += c[nt][2] * c[nt][2] + c[nt][3] * c[nt][3];
    }
    s0 += __shfl_xor_sync(0xFFFFFFFF, s0, 1);
    s0 += __shfl_xor_sync(0xFFFFFFFF, s0, 2);
    s1 += __shfl_xor_sync(0xFFFFFFFF, s1, 1);
    s1 += __shfl_xor_sync(0xFFFFFFFF, s1, 2);
    if ((l & 3) == 0) {
        int r0 = w * 16 + (l >> 2);
        out[(size_t)(b0 + (r0 >> 6)) * 192 + 128 + (r0 & 63)] = sqrtf(s0);
        int r1 = r0 + 8;
        out[(size_t)(b0 + (r1 >> 6)) * 192 + 128 + (r1 & 63)] = sqrtf(s1);
    }
}

__global__ __launch_bounds__(256) void z_kernel(const float* __restrict__ Wout,
                                                float* __restrict__ out)
{
    extern __shared__ char smz[];
    uint32_t smu = smem_u32(smz);
    int t = threadIdx.x;
    int b0 = blockIdx.x * 2;

    if (t == 0) {
        volatile unsigned* f = g_flag;
        while (!f[blockIdx.x >> 2]) __nanosleep(64);
    }
    __syncthreads();
    __threadfence();

    char* sAc = smz + ZP_A;
    const float* d3b = g_maskB + ((size_t)2 * BATCH + b0) * HID;
    for (int i = t; i < 128 * 256; i += 256) {
        int m = i >> 8, h = (i & 255) * 2;
        int item = m >> 6, n = m & 63;
        const float* d3 = d3b + item * HID;
        *(uint32_t*)(sAc + m * A_STRIDE + h * 2) =
            pack_bf16(Wout[n * HID + h] * d3[h], Wout[n * HID + h + 1] * d3[h + 1]);
    }

    __nv_bfloat16* Ug = g_U + (size_t)blockIdx.x * 128 * HID;
    gemm512(g_WT[1], g_maskB + ((size_t)1 * BATCH + b0) * HID, Ug, smu, t);
    gemm512(g_WT[0], g_maskB + ((size_t)0 * BATCH + b0) * HID, Ug, smu, t);
    gemm_final(g_G0T, out, b0, smu, t);
}

// ---------------- launch ----------------
extern "C" void kernel_launch(void* const* d_in, const int* in_sizes, int n_in,
                              void* d_out, int out_size)
{
    const float* x    = (const float*)d_in[0];
    const float* Win  = (const float*)d_in[1];
    const float* bin  = (const float*)d_in[2];
    const float* Wh   = (const float*)d_in[3];
    const float* bh   = (const float*)d_in[4];
    const float* Wout = (const float*)d_in[5];
    const float* bout = (const float*)d_in[6];
    float* out = (float*)d_out;

    int B = in_sizes[0] / 192;   // 4096

    const int fwd_smem = (GB * (3 * NDIM + 3 * HID)) * sizeof(float);   // 55296
    cudaFuncSetAttribute(fwd_kernel, cudaFuncAttributeMaxDynamicSharedMemorySize, fwd_smem);
    cudaFuncSetAttribute(z_kernel,   cudaFuncAttributeMaxDynamicSharedMemorySize, Z_SMEM);

    prep_reset<<<8, 64>>>();
    prep_g0<<<HID, NDIM>>>(Wh, Win);
    prep_wt<<<1024, 128>>>(Wh);
    prep_g0t<<<NDIM, HID>>>();
    prep_wp<<<3 * 256, 512>>>(Wh);
    prep_winp<<<256, NDIM>>>(Win);
    prep_woutt<<<HID, NDIM>>>(Wout);
    fwd_kernel<<<B / GB, 256, fwd_smem>>>(x, bin, bh, bout, out);

    // z: programmatic dependent launch — may start while fwd is still running;
    // per-block flags enforce the real data dependency.
    cudaLaunchConfig_t cfg = {};
    cfg.gridDim = dim3(B / 2);
    cfg.blockDim = dim3(256);
    cfg.dynamicSmemBytes = Z_SMEM;
    cfg.stream = 0;
    cudaLaunchAttribute at[1];
    at[0].id = cudaLaunchAttributeProgrammaticStreamSerialization;
    at[0].val.programmaticStreamSerializationAllowed = 1;
    cfg.attrs = at;
    cfg.numAttrs = 1;
    cudaError_t e = cudaLaunchKernelEx(&cfg, z_kernel, Wout, out);
    if (e != cudaSuccess)
        z_kernel<<<B / 2, 256, Z_SMEM>>>(Wout, out);
}